// round 1
// baseline (speedup 1.0000x reference)
#include <cuda_runtime.h>
#include <cstdint>

// DynamicConv2d: B=64, C=8, H=W=256, OUT_C=8, K=3, IN_FEAT=8
// Stage 1: generate per-sample 3x3 kernels (tiny GEMM), store as
//          broadcast-duplicated f32 pairs for FFMA2 consumption.
// Stage 2: direct conv, f32x2-packed over adjacent x pixels.
//          Input rows stored in smem at TWO alignments so all three
//          kx-shifted 64-bit pairs are aligned LDS.64 (no pack MOVs).

typedef unsigned long long ull;

#define NB   64
#define NC   8
#define NOC  8
#define HW   256

// scratch: 64 samples * 576 weights * 2 (duplicated pair halves)
__device__ float g_wp[NB * 1152];

// ---------------- Stage 1: weight generation ----------------
// pair index p = (ci*9 + ky*3 + kx)*8 + o
// value(p) = sum_i dw[b, o=p&7, i] * Wg[(p>>3)*8 + i] + bg[p>>3]
__global__ void gen_weights_kernel(const float* __restrict__ dw,
                                   const float* __restrict__ Wg,
                                   const float* __restrict__ bg) {
    int b = blockIdx.x;
    int p = threadIdx.x;
    if (p >= 576) return;
    int o = p & 7;
    int j = p >> 3;
    float s = bg[j];
    const float* dwp = dw + b * 64 + o * 8;
    const float* wgp = Wg + j * 8;
#pragma unroll
    for (int i = 0; i < 8; i++) s = fmaf(dwp[i], wgp[i], s);
    g_wp[b * 1152 + 2 * p]     = s;   // broadcast pair (s, s)
    g_wp[b * 1152 + 2 * p + 1] = s;
}

// ---------------- Stage 2: convolution ----------------

__device__ __forceinline__ ull fma2(ull a, ull b, ull c) {
    ull d;
    asm("fma.rn.f32x2 %0, %1, %2, %3;" : "=l"(d) : "l"(a), "l"(b), "l"(c));
    return d;
}

__device__ __forceinline__ void cp4(uint32_t saddr, const void* g, int srcsz) {
    asm volatile("cp.async.ca.shared.global [%0], [%1], %2, %3;\n"
                 :: "r"(saddr), "l"(g), "n"(4), "r"(srcsz));
}

#define SROWS 34          // 32 output rows + 2 halo
#define RST   136         // row stride in floats: C2[0..65], pad, C1 at 72..135
#define BUFSZ (SROWS * RST)

// block: 256 threads = 32 x-threads (2 px each -> 64 wide) x 8 y-threads (4 rows each -> 32 tall)
// grid: (256/64, 256/32, 64)
__global__ void __launch_bounds__(256) conv_kernel(const float* __restrict__ x,
                                                   float* __restrict__ out) {
    __shared__ alignas(16) float sb[2 * BUFSZ + 1152];
    float* ws = sb + 2 * BUFSZ;

    const int b  = blockIdx.z;
    const int x0 = blockIdx.x * 64;
    const int y0 = blockIdx.y * 32;
    const int tid = threadIdx.x;
    const int xt = tid & 31;
    const int ty = tid >> 5;

    // weights: global (already duplicated pairs) -> smem
    for (int i = tid; i < 1152; i += 256) ws[i] = g_wp[b * 1152 + i];

    auto load_tile = [&](int bufi, int c) {
        float* dst = sb + bufi * BUFSZ;
        uint32_t sbase = (uint32_t)__cvta_generic_to_shared(dst);
        const float* xp = x + ((size_t)(b * NC + c)) * (HW * HW);
        for (int i = tid; i < SROWS * 66; i += 256) {
            int rr = i / 66;
            int k  = i - rr * 66;            // gx = x0 - 1 + k, k in [0,66)
            int gy = y0 - 1 + rr;
            int gx = x0 - 1 + k;
            bool inb = ((unsigned)gy < (unsigned)HW) && ((unsigned)gx < (unsigned)HW);
            const float* src = xp + (inb ? (gy * HW + gx) : 0);
            int sz = inb ? 4 : 0;
            // C2[k] = in[x0-1+k]  (odd-shifted copy)
            cp4(sbase + (uint32_t)(rr * RST + k) * 4u, src, sz);
            // C1[k-1] = in[x0+(k-1)]  (even-aligned copy)
            if (k >= 1 && k <= 64)
                cp4(sbase + (uint32_t)(rr * RST + 72 + (k - 1)) * 4u, src, sz);
        }
    };

    ull acc[4][8];
#pragma unroll
    for (int r = 0; r < 4; r++)
#pragma unroll
        for (int o = 0; o < 8; o++) acc[r][o] = 0ull;

    // prologue: channel 0 into buffer 0
    load_tile(0, 0);
    asm volatile("cp.async.commit_group;\n");
    asm volatile("cp.async.wait_group 0;\n");
    __syncthreads();

    for (int c = 0; c < NC; c++) {
        if (c < NC - 1) {
            load_tile((c + 1) & 1, c + 1);
            asm volatile("cp.async.commit_group;\n");
        }
        const float* cb = sb + (c & 1) * BUFSZ;
#pragma unroll
        for (int ky = 0; ky < 3; ky++) {
            // 24 broadcast weight pairs for (c, ky): index kx*8 + o
            ull w2[24];
            const ulonglong2* wv = (const ulonglong2*)ws + (c * 3 + ky) * 12;
#pragma unroll
            for (int j = 0; j < 12; j++) {
                ulonglong2 u = wv[j];
                w2[2 * j]     = u.x;
                w2[2 * j + 1] = u.y;
            }
#pragma unroll
            for (int r = 0; r < 4; r++) {
                const float* rp = cb + (ty * 4 + r + ky) * RST;
                // pixels px0 = x0 + 2*xt, px0+1
                ull pa = *(const ull*)(rp + 2 * xt);          // (in[px0-1], in[px0])   kx=0
                ull pc = *(const ull*)(rp + 2 * xt + 2);      // (in[px0+1], in[px0+2]) kx=2
                ull pb = *(const ull*)(rp + 72 + 2 * xt);     // (in[px0],   in[px0+1]) kx=1
#pragma unroll
                for (int o = 0; o < 8; o++) acc[r][o] = fma2(pa, w2[o],      acc[r][o]);
#pragma unroll
                for (int o = 0; o < 8; o++) acc[r][o] = fma2(pb, w2[8 + o],  acc[r][o]);
#pragma unroll
                for (int o = 0; o < 8; o++) acc[r][o] = fma2(pc, w2[16 + o], acc[r][o]);
            }
        }
        if (c < NC - 1) asm volatile("cp.async.wait_group 0;\n");
        __syncthreads();
    }

    // epilogue: each acc pair is two adjacent x outputs -> 8-byte store
#pragma unroll
    for (int r = 0; r < 4; r++) {
        int gy = y0 + ty * 4 + r;
#pragma unroll
        for (int o = 0; o < 8; o++) {
            size_t idx = ((size_t)(b * NOC + o)) * (HW * HW) + (size_t)gy * HW + x0 + 2 * xt;
            *(ull*)(out + idx) = acc[r][o];
        }
    }
}

extern "C" void kernel_launch(void* const* d_in, const int* in_sizes, int n_in,
                              void* d_out, int out_size) {
    const float* x  = (const float*)d_in[0];
    const float* dw = (const float*)d_in[1];
    const float* Wg = (const float*)d_in[2];
    const float* bg = (const float*)d_in[3];
    float* out = (float*)d_out;

    gen_weights_kernel<<<NB, 576>>>(dw, Wg, bg);

    dim3 grid(HW / 64, HW / 32, NB);
    conv_kernel<<<grid, 256>>>(x, out);
}